// round 3
// baseline (speedup 1.0000x reference)
#include <cuda_runtime.h>
#include <cstdint>

#define FULL 0xFFFFFFFFu

constexpr int N_RAYS    = 8192;
constexpr int N_SAMPLES = 512;
constexpr int HID       = 32;
constexpr int WARPS_PER_BLOCK = 8;
constexpr int TPT       = 16;   // samples per thread

using ull = unsigned long long;

// ---- packed f32x2 helpers (sm_103a) ----
__device__ __forceinline__ ull pk2(float lo, float hi) {
    ull r; asm("mov.b64 %0, {%1, %2};" : "=l"(r) : "f"(lo), "f"(hi)); return r;
}
__device__ __forceinline__ void upk2(ull v, float& lo, float& hi) {
    asm("mov.b64 {%0, %1}, %2;" : "=f"(lo), "=f"(hi) : "l"(v));
}
__device__ __forceinline__ ull fma2_(ull a, ull b, ull c) {
    ull r; asm("fma.rn.f32x2 %0, %1, %2, %3;" : "=l"(r) : "l"(a), "l"(b), "l"(c)); return r;
}
__device__ __forceinline__ ull add2_(ull a, ull b) {
    ull r; asm("add.rn.f32x2 %0, %1, %2;" : "=l"(r) : "l"(a), "l"(b)); return r;
}
// 2*relu(x) per half: x + |x|   (layer-2 weights pre-scaled by 0.5)
__device__ __forceinline__ ull relu2x(ull h) {
    union { ull u; uint2 v; } a, m;
    a.u = h;
    m.v.x = a.v.x & 0x7fffffffu;
    m.v.y = a.v.y & 0x7fffffffu;
    return add2_(h, m.u);
}

__device__ __forceinline__ float sigmoidf_fast(float x) {
    return __fdividef(1.0f, 1.0f + __expf(-x));
}
__device__ __forceinline__ float softplusf_fast(float x) {
    return fmaxf(x, 0.0f) + __logf(1.0f + __expf(-fabsf(x)));
}

__global__ __launch_bounds__(WARPS_PER_BLOCK * 32, 2)
void nerf_render_kernel(
    const float* __restrict__ o,    // [N,3]
    const float* __restrict__ dI,   // [N,3]
    const float* __restrict__ aabb, // [2,3]
    const float* __restrict__ u,    // [N,512]
    const float* __restrict__ W1,   // [3,32]
    const float* __restrict__ b1,   // [32]
    const float* __restrict__ Wc,   // [32,3]
    const float* __restrict__ bc,   // [3]
    const float* __restrict__ Wd,   // [32,1]
    const float* __restrict__ bd,   // [1]
    float* __restrict__ out)        // [N,4]
{
    // weight tables: each entry = two duplicated (w,w) f32x2 packs -> one LDS.128
    // sAB[j] = { (wx,wx), (wy,wy) }   sCD[j] = { (wz,wz), (b1,b1) }
    // sEF[j] = { (.5cx,.5cx), (.5cy,.5cy) }  sGH[j] = { (.5cz,.5cz), (.5cw,.5cw) }
    __shared__ ulonglong2 sAB[HID], sCD[HID], sEF[HID], sGH[HID];
    __shared__ float sbias[4];

    const int tx = threadIdx.x;
    if (tx < HID) {
        const float wx = W1[tx], wy = W1[HID + tx], wz = W1[2 * HID + tx], wb = b1[tx];
        sAB[tx] = make_ulonglong2(pk2(wx, wx), pk2(wy, wy));
        sCD[tx] = make_ulonglong2(pk2(wz, wz), pk2(wb, wb));
        const float cx = 0.5f * Wc[3 * tx], cy = 0.5f * Wc[3 * tx + 1];
        const float cz = 0.5f * Wc[3 * tx + 2], cw = 0.5f * Wd[tx];
        sEF[tx] = make_ulonglong2(pk2(cx, cx), pk2(cy, cy));
        sGH[tx] = make_ulonglong2(pk2(cz, cz), pk2(cw, cw));
    }
    if (tx == HID) { sbias[0] = bc[0]; sbias[1] = bc[1]; sbias[2] = bc[2]; sbias[3] = bd[0]; }
    __syncthreads();

    const int warp = tx >> 5;
    const int lane = tx & 31;
    const int r = blockIdx.x * WARPS_PER_BLOCK + warp;

    const float ox = o[3 * r], oy = o[3 * r + 1], oz = o[3 * r + 2];
    const float dx = dI[3 * r], dy = dI[3 * r + 1], dz = dI[3 * r + 2];
    const float mn0 = aabb[0], mn1 = aabb[1], mn2 = aabb[2];
    const float mx0 = aabb[3], mx1 = aabb[4], mx2 = aabb[5];

    float t1, t2;
    t1 = (mn0 - ox) / dx; t2 = (mx0 - ox) / dx;
    float tn = fminf(t1, t2), tf = fmaxf(t1, t2);
    t1 = (mn1 - oy) / dy; t2 = (mx1 - oy) / dy;
    tn = fmaxf(tn, fminf(t1, t2)); tf = fminf(tf, fmaxf(t1, t2));
    t1 = (mn2 - oz) / dz; t2 = (mx2 - oz) / dz;
    tn = fmaxf(tn, fminf(t1, t2)); tf = fminf(tf, fmaxf(t1, t2));
    tn = fmaxf(tn, 0.0f);

    if (!(tn < tf)) {
        if (lane == 0) reinterpret_cast<float4*>(out)[r] = make_float4(0.f, 0.f, 0.f, 0.f);
        return;
    }

    const float dnorm  = sqrtf(dx * dx + dy * dy + dz * dz);
    const float scaleT = (tf - tn) * (1.0f / (float)N_SAMPLES);
    const float dscale = scaleT * dnorm;
    const float g0 = 2.0f / (mx0 - mn0);
    const float g1 = 2.0f / (mx1 - mn1);
    const float g2 = 2.0f / (mx2 - mn2);
    const float bcr = sbias[0], bcg = sbias[1], bcb = sbias[2], bdd = sbias[3];

    const float2* u2 = reinterpret_cast<const float2*>(u + (size_t)r * N_SAMPLES) + lane * (TPT / 2);
    // neighbor lane's first u (feeds lane's last delta; lane 31 takes the t==511 path)
    float2 f2 = u2[0];
    const float nb = __shfl_down_sync(FULL, f2.x, 1);

    const int base = lane * TPT;

    float e_run = 1.0f, Psum = 0.0f;
    float ar = 0.f, ag = 0.f, ab = 0.f, aw = 0.f;

    #pragma unroll 1
    for (int i = 0; i < TPT / 2; ++i) {
        const float u0 = f2.x, u1 = f2.y;
        float un;
        if (i < TPT / 2 - 1) { f2 = u2[i + 1]; un = f2.x; }
        else                 { un = nb; }
        const int t0 = base + 2 * i;

        // ---- geometry for the 2 samples
        float n00, n01, n02, n10, n11, n12, ts1;
        {
            const float ts = fmaf(scaleT, (float)t0 + u0, tn);
            const float x = fmaf(dx, ts, ox), y = fmaf(dy, ts, oy), z = fmaf(dz, ts, oz);
            n00 = fmaf(x - mn0, g0, -1.0f); n01 = fmaf(y - mn1, g1, -1.0f); n02 = fmaf(z - mn2, g2, -1.0f);
        }
        {
            ts1 = fmaf(scaleT, (float)(t0 + 1) + u1, tn);
            const float x = fmaf(dx, ts1, ox), y = fmaf(dy, ts1, oy), z = fmaf(dz, ts1, oz);
            n10 = fmaf(x - mn0, g0, -1.0f); n11 = fmaf(y - mn1, g1, -1.0f); n12 = fmaf(z - mn2, g2, -1.0f);
        }
        const bool ib0 = (fabsf(n00) <= 1.f) & (fabsf(n01) <= 1.f) & (fabsf(n02) <= 1.f);
        const bool ib1 = (fabsf(n10) <= 1.f) & (fabsf(n11) <= 1.f) & (fabsf(n12) <= 1.f);
        const float dl0 = dscale * (1.0f + u1 - u0);
        float dl1 = dscale * (1.0f + un - u1);
        if (t0 + 1 == N_SAMPLES - 1) dl1 = (tf + 1.0f - ts1) * dnorm;

        // ---- packed MLP for the sample pair
        const ull pn0 = pk2(n00, n10), pn1 = pk2(n01, n11), pn2 = pk2(n02, n12);

        ull pr = 0, pg = 0, pb = 0, pd = 0;
        #pragma unroll
        for (int j = 0; j < HID; ++j) {
            const ulonglong2 wab = sAB[j];
            const ulonglong2 wcd = sCD[j];
            ull h = fma2_(pn0, wab.x, fma2_(pn1, wab.y, fma2_(pn2, wcd.x, wcd.y)));
            h = relu2x(h);
            const ulonglong2 wef = sEF[j];
            const ulonglong2 wgh = sGH[j];
            pr = fma2_(h, wef.x, pr); pg = fma2_(h, wef.y, pg);
            pb = fma2_(h, wgh.x, pb); pd = fma2_(h, wgh.y, pd);
        }

        float c0r, c1r, c0g, c1g, c0b, c1b, d0, d1;
        upk2(pr, c0r, c1r); upk2(pg, c0g, c1g); upk2(pb, c0b, c1b); upk2(pd, d0, d1);

        // ---- sequential compositing (order matters)
        {
            const float cr = sigmoidf_fast(c0r + bcr), cg = sigmoidf_fast(c0g + bcg), cb = sigmoidf_fast(c0b + bcb);
            float den = softplusf_fast(d0 + bdd); if (!ib0) den = 0.0f;
            const float sd = den * dl0, esd = __expf(-sd);
            const float wl = e_run - e_run * esd;
            ar = fmaf(wl, cr, ar); ag = fmaf(wl, cg, ag); ab = fmaf(wl, cb, ab); aw += wl;
            e_run *= esd; Psum += sd;
        }
        {
            const float cr = sigmoidf_fast(c1r + bcr), cg = sigmoidf_fast(c1g + bcg), cb = sigmoidf_fast(c1b + bcb);
            float den = softplusf_fast(d1 + bdd); if (!ib1) den = 0.0f;
            const float sd = den * dl1, esd = __expf(-sd);
            const float wl = e_run - e_run * esd;
            ar = fmaf(wl, cr, ar); ag = fmaf(wl, cg, ag); ab = fmaf(wl, cb, ab); aw += wl;
            e_run *= esd; Psum += sd;
        }
    }

    // ---- warp exclusive scan of optical depth -> per-lane transmittance base
    float inc = Psum;
    #pragma unroll
    for (int off = 1; off < 32; off <<= 1) {
        float y = __shfl_up_sync(FULL, inc, off);
        if (lane >= off) inc += y;
    }
    float excl = __shfl_up_sync(FULL, inc, 1);
    if (lane == 0) excl = 0.0f;
    const float sc = __expf(-excl);
    ar *= sc; ag *= sc; ab *= sc; aw *= sc;

    #pragma unroll
    for (int off = 16; off > 0; off >>= 1) {
        ar += __shfl_xor_sync(FULL, ar, off);
        ag += __shfl_xor_sync(FULL, ag, off);
        ab += __shfl_xor_sync(FULL, ab, off);
        aw += __shfl_xor_sync(FULL, aw, off);
    }

    if (lane == 0)
        reinterpret_cast<float4*>(out)[r] = make_float4(ar, ag, ab, aw);
}

extern "C" void kernel_launch(void* const* d_in, const int* in_sizes, int n_in,
                              void* d_out, int out_size) {
    const float* o    = (const float*)d_in[0];
    const float* dI   = (const float*)d_in[1];
    const float* aabb = (const float*)d_in[2];
    const float* u    = (const float*)d_in[3];
    const float* W1   = (const float*)d_in[4];
    const float* b1   = (const float*)d_in[5];
    const float* Wc   = (const float*)d_in[6];
    const float* bc   = (const float*)d_in[7];
    const float* Wd   = (const float*)d_in[8];
    const float* bd   = (const float*)d_in[9];
    float* out = (float*)d_out;

    dim3 grid(N_RAYS / WARPS_PER_BLOCK);
    dim3 block(WARPS_PER_BLOCK * 32);
    nerf_render_kernel<<<grid, block>>>(o, dI, aabb, u, W1, b1, Wc, bc, Wd, bd, out);
}

// round 4
// speedup vs baseline: 5.3773x; 5.3773x over previous
#include <cuda_runtime.h>
#include <cstdint>

#define FULL 0xFFFFFFFFu

constexpr int N_RAYS    = 8192;
constexpr int N_SAMPLES = 512;
constexpr int HID       = 32;
constexpr int WARPS_PER_BLOCK = 8;
constexpr int TPT       = 16;   // samples per thread

using ull = unsigned long long;

// ---- packed f32x2 helpers (sm_103a) ----
__device__ __forceinline__ ull pk2(float lo, float hi) {
    ull r; asm("mov.b64 %0, {%1, %2};" : "=l"(r) : "f"(lo), "f"(hi)); return r;
}
__device__ __forceinline__ void upk2(ull v, float& lo, float& hi) {
    asm("mov.b64 {%0, %1}, %2;" : "=f"(lo), "=f"(hi) : "l"(v));
}
__device__ __forceinline__ ull fma2_(ull a, ull b, ull c) {
    ull r; asm("fma.rn.f32x2 %0, %1, %2, %3;" : "=l"(r) : "l"(a), "l"(b), "l"(c)); return r;
}
__device__ __forceinline__ ull add2_(ull a, ull b) {
    ull r; asm("add.rn.f32x2 %0, %1, %2;" : "=l"(r) : "l"(a), "l"(b)); return r;
}
// 2*relu(x) per half: x + |x|   (layer-2 weights pre-scaled by 0.5)
__device__ __forceinline__ ull relu2x(ull h) {
    union { ull u; uint2 v; } a, m;
    a.u = h;
    m.v.x = a.v.x & 0x7fffffffu;
    m.v.y = a.v.y & 0x7fffffffu;
    return add2_(h, m.u);
}

__device__ __forceinline__ float sigmoidf_fast(float x) {
    return __fdividef(1.0f, 1.0f + __expf(-x));
}
__device__ __forceinline__ float softplusf_fast(float x) {
    return fmaxf(x, 0.0f) + __logf(1.0f + __expf(-fabsf(x)));
}

__global__ __launch_bounds__(WARPS_PER_BLOCK * 32)
void nerf_render_kernel(
    const float* __restrict__ o,    // [N,3]
    const float* __restrict__ dI,   // [N,3]
    const float* __restrict__ aabb, // [2,3]
    const float* __restrict__ u,    // [N,512]
    const float* __restrict__ W1,   // [3,32]
    const float* __restrict__ b1,   // [32]
    const float* __restrict__ Wc,   // [32,3]
    const float* __restrict__ bc,   // [3]
    const float* __restrict__ Wd,   // [32,1]
    const float* __restrict__ bd,   // [1]
    float* __restrict__ out)        // [N,4]
{
    // weight tables: each entry = two duplicated (w,w) f32x2 packs -> one LDS.128
    __shared__ ulonglong2 sAB[HID], sCD[HID], sEF[HID], sGH[HID];
    __shared__ float sbias[4];

    const int tx = threadIdx.x;
    if (tx < HID) {
        const float wx = W1[tx], wy = W1[HID + tx], wz = W1[2 * HID + tx], wb = b1[tx];
        sAB[tx] = make_ulonglong2(pk2(wx, wx), pk2(wy, wy));
        sCD[tx] = make_ulonglong2(pk2(wz, wz), pk2(wb, wb));
        const float cx = 0.5f * Wc[3 * tx], cy = 0.5f * Wc[3 * tx + 1];
        const float cz = 0.5f * Wc[3 * tx + 2], cw = 0.5f * Wd[tx];
        sEF[tx] = make_ulonglong2(pk2(cx, cx), pk2(cy, cy));
        sGH[tx] = make_ulonglong2(pk2(cz, cz), pk2(cw, cw));
    }
    if (tx == HID) { sbias[0] = bc[0]; sbias[1] = bc[1]; sbias[2] = bc[2]; sbias[3] = bd[0]; }
    __syncthreads();

    const int warp = tx >> 5;
    const int lane = tx & 31;
    const int r = blockIdx.x * WARPS_PER_BLOCK + warp;

    const float ox = o[3 * r], oy = o[3 * r + 1], oz = o[3 * r + 2];
    const float dx = dI[3 * r], dy = dI[3 * r + 1], dz = dI[3 * r + 2];
    const float mn0 = aabb[0], mn1 = aabb[1], mn2 = aabb[2];
    const float mx0 = aabb[3], mx1 = aabb[4], mx2 = aabb[5];

    float t1, t2;
    t1 = (mn0 - ox) / dx; t2 = (mx0 - ox) / dx;
    float tn = fminf(t1, t2), tf = fmaxf(t1, t2);
    t1 = (mn1 - oy) / dy; t2 = (mx1 - oy) / dy;
    tn = fmaxf(tn, fminf(t1, t2)); tf = fminf(tf, fmaxf(t1, t2));
    t1 = (mn2 - oz) / dz; t2 = (mx2 - oz) / dz;
    tn = fmaxf(tn, fminf(t1, t2)); tf = fminf(tf, fmaxf(t1, t2));
    tn = fmaxf(tn, 0.0f);

    if (!(tn < tf)) {
        if (lane == 0) reinterpret_cast<float4*>(out)[r] = make_float4(0.f, 0.f, 0.f, 0.f);
        return;
    }

    const float dnorm  = sqrtf(dx * dx + dy * dy + dz * dz);
    const float scaleT = (tf - tn) * (1.0f / (float)N_SAMPLES);
    const float dscale = scaleT * dnorm;
    const float g0 = 2.0f / (mx0 - mn0);
    const float g1 = 2.0f / (mx1 - mn1);
    const float g2 = 2.0f / (mx2 - mn2);
    const float bcr = sbias[0], bcg = sbias[1], bcb = sbias[2], bdd = sbias[3];

    const float2* u2 = reinterpret_cast<const float2*>(u + (size_t)r * N_SAMPLES) + lane * (TPT / 2);
    float2 f2 = u2[0];
    const float nb = __shfl_down_sync(FULL, f2.x, 1);

    const int base = lane * TPT;

    float e_run = 1.0f, Psum = 0.0f;
    float ar = 0.f, ag = 0.f, ab = 0.f, aw = 0.f;

    #pragma unroll 1
    for (int i = 0; i < TPT / 2; ++i) {
        const float u0 = f2.x, u1 = f2.y;
        float un;
        if (i < TPT / 2 - 1) { f2 = u2[i + 1]; un = f2.x; }
        else                 { un = nb; }
        const int t0 = base + 2 * i;

        // ---- geometry for the 2 samples
        float n00, n01, n02, n10, n11, n12, ts1;
        {
            const float ts = fmaf(scaleT, (float)t0 + u0, tn);
            const float x = fmaf(dx, ts, ox), y = fmaf(dy, ts, oy), z = fmaf(dz, ts, oz);
            n00 = fmaf(x - mn0, g0, -1.0f); n01 = fmaf(y - mn1, g1, -1.0f); n02 = fmaf(z - mn2, g2, -1.0f);
        }
        {
            ts1 = fmaf(scaleT, (float)(t0 + 1) + u1, tn);
            const float x = fmaf(dx, ts1, ox), y = fmaf(dy, ts1, oy), z = fmaf(dz, ts1, oz);
            n10 = fmaf(x - mn0, g0, -1.0f); n11 = fmaf(y - mn1, g1, -1.0f); n12 = fmaf(z - mn2, g2, -1.0f);
        }
        const bool ib0 = (fabsf(n00) <= 1.f) & (fabsf(n01) <= 1.f) & (fabsf(n02) <= 1.f);
        const bool ib1 = (fabsf(n10) <= 1.f) & (fabsf(n11) <= 1.f) & (fabsf(n12) <= 1.f);
        const float dl0 = dscale * (1.0f + u1 - u0);
        float dl1 = dscale * (1.0f + un - u1);
        if (t0 + 1 == N_SAMPLES - 1) dl1 = (tf + 1.0f - ts1) * dnorm;

        // ---- packed MLP for the sample pair (bounded unroll to cap LDS hoisting)
        const ull pn0 = pk2(n00, n10), pn1 = pk2(n01, n11), pn2 = pk2(n02, n12);

        ull pr = 0, pg = 0, pb = 0, pd = 0;
        #pragma unroll 8
        for (int j = 0; j < HID; ++j) {
            const ulonglong2 wab = sAB[j];
            const ulonglong2 wcd = sCD[j];
            ull h = fma2_(pn0, wab.x, fma2_(pn1, wab.y, fma2_(pn2, wcd.x, wcd.y)));
            h = relu2x(h);
            const ulonglong2 wef = sEF[j];
            const ulonglong2 wgh = sGH[j];
            pr = fma2_(h, wef.x, pr); pg = fma2_(h, wef.y, pg);
            pb = fma2_(h, wgh.x, pb); pd = fma2_(h, wgh.y, pd);
        }

        float c0r, c1r, c0g, c1g, c0b, c1b, d0, d1;
        upk2(pr, c0r, c1r); upk2(pg, c0g, c1g); upk2(pb, c0b, c1b); upk2(pd, d0, d1);

        // ---- sequential compositing (order matters)
        {
            const float cr = sigmoidf_fast(c0r + bcr), cg = sigmoidf_fast(c0g + bcg), cb = sigmoidf_fast(c0b + bcb);
            float den = softplusf_fast(d0 + bdd); if (!ib0) den = 0.0f;
            const float sd = den * dl0, esd = __expf(-sd);
            const float wl = e_run - e_run * esd;
            ar = fmaf(wl, cr, ar); ag = fmaf(wl, cg, ag); ab = fmaf(wl, cb, ab); aw += wl;
            e_run *= esd; Psum += sd;
        }
        {
            const float cr = sigmoidf_fast(c1r + bcr), cg = sigmoidf_fast(c1g + bcg), cb = sigmoidf_fast(c1b + bcb);
            float den = softplusf_fast(d1 + bdd); if (!ib1) den = 0.0f;
            const float sd = den * dl1, esd = __expf(-sd);
            const float wl = e_run - e_run * esd;
            ar = fmaf(wl, cr, ar); ag = fmaf(wl, cg, ag); ab = fmaf(wl, cb, ab); aw += wl;
            e_run *= esd; Psum += sd;
        }
    }

    // ---- warp exclusive scan of optical depth -> per-lane transmittance base
    float inc = Psum;
    #pragma unroll
    for (int off = 1; off < 32; off <<= 1) {
        float y = __shfl_up_sync(FULL, inc, off);
        if (lane >= off) inc += y;
    }
    float excl = __shfl_up_sync(FULL, inc, 1);
    if (lane == 0) excl = 0.0f;
    const float sc = __expf(-excl);
    ar *= sc; ag *= sc; ab *= sc; aw *= sc;

    #pragma unroll
    for (int off = 16; off > 0; off >>= 1) {
        ar += __shfl_xor_sync(FULL, ar, off);
        ag += __shfl_xor_sync(FULL, ag, off);
        ab += __shfl_xor_sync(FULL, ab, off);
        aw += __shfl_xor_sync(FULL, aw, off);
    }

    if (lane == 0)
        reinterpret_cast<float4*>(out)[r] = make_float4(ar, ag, ab, aw);
}

extern "C" void kernel_launch(void* const* d_in, const int* in_sizes, int n_in,
                              void* d_out, int out_size) {
    const float* o    = (const float*)d_in[0];
    const float* dI   = (const float*)d_in[1];
    const float* aabb = (const float*)d_in[2];
    const float* u    = (const float*)d_in[3];
    const float* W1   = (const float*)d_in[4];
    const float* b1   = (const float*)d_in[5];
    const float* Wc   = (const float*)d_in[6];
    const float* bc   = (const float*)d_in[7];
    const float* Wd   = (const float*)d_in[8];
    const float* bd   = (const float*)d_in[9];
    float* out = (float*)d_out;

    dim3 grid(N_RAYS / WARPS_PER_BLOCK);
    dim3 block(WARPS_PER_BLOCK * 32);
    nerf_render_kernel<<<grid, block>>>(o, dI, aabb, u, W1, b1, Wc, bc, Wd, bd, out);
}

// round 5
// speedup vs baseline: 6.2048x; 1.1539x over previous
#include <cuda_runtime.h>
#include <cstdint>

#define FULL 0xFFFFFFFFu

constexpr int N_RAYS    = 8192;
constexpr int N_SAMPLES = 512;
constexpr int HID       = 32;
constexpr int WARPS_PER_BLOCK = 8;
constexpr int TPT       = 16;   // samples per thread

using ull = unsigned long long;

// ---- packed f32x2 helpers (sm_103a) ----
__device__ __forceinline__ ull pk2(float lo, float hi) {
    ull r; asm("mov.b64 %0, {%1, %2};" : "=l"(r) : "f"(lo), "f"(hi)); return r;
}
__device__ __forceinline__ void upk2(ull v, float& lo, float& hi) {
    asm("mov.b64 {%0, %1}, %2;" : "=f"(lo), "=f"(hi) : "l"(v));
}
__device__ __forceinline__ ull fma2_(ull a, ull b, ull c) {
    ull r; asm("fma.rn.f32x2 %0, %1, %2, %3;" : "=l"(r) : "l"(a), "l"(b), "l"(c)); return r;
}
__device__ __forceinline__ ull add2_(ull a, ull b) {
    ull r; asm("add.rn.f32x2 %0, %1, %2;" : "=l"(r) : "l"(a), "l"(b)); return r;
}
// 2*relu(x) per half: x + |x|   (layer-2 weights pre-scaled by 0.5)
__device__ __forceinline__ ull relu2x(ull h) {
    union { ull u; uint2 v; } a, m;
    a.u = h;
    m.v.x = a.v.x & 0x7fffffffu;
    m.v.y = a.v.y & 0x7fffffffu;
    return add2_(h, m.u);
}

__device__ __forceinline__ float sigmoidf_fast(float x) {
    return __fdividef(1.0f, 1.0f + __expf(-x));
}
__device__ __forceinline__ float softplusf_fast(float x) {
    return fmaxf(x, 0.0f) + __logf(1.0f + __expf(-fabsf(x)));
}

__global__ __launch_bounds__(WARPS_PER_BLOCK * 32)
void nerf_render_kernel(
    const float* __restrict__ o,    // [N,3]
    const float* __restrict__ dI,   // [N,3]
    const float* __restrict__ aabb, // [2,3]
    const float* __restrict__ u,    // [N,512]
    const float* __restrict__ W1,   // [3,32]
    const float* __restrict__ b1,   // [32]
    const float* __restrict__ Wc,   // [32,3]
    const float* __restrict__ bc,   // [3]
    const float* __restrict__ Wd,   // [32,1]
    const float* __restrict__ bd,   // [1]
    float* __restrict__ out)        // [N,4]
{
    // weight tables: each entry = two duplicated (w,w) f32x2 packs -> one LDS.128
    __shared__ ulonglong2 sAB[HID], sCD[HID], sEF[HID], sGH[HID];
    __shared__ float sbias[4];

    const int tx = threadIdx.x;
    if (tx < HID) {
        const float wx = W1[tx], wy = W1[HID + tx], wz = W1[2 * HID + tx], wb = b1[tx];
        sAB[tx] = make_ulonglong2(pk2(wx, wx), pk2(wy, wy));
        sCD[tx] = make_ulonglong2(pk2(wz, wz), pk2(wb, wb));
        const float cx = 0.5f * Wc[3 * tx], cy = 0.5f * Wc[3 * tx + 1];
        const float cz = 0.5f * Wc[3 * tx + 2], cw = 0.5f * Wd[tx];
        sEF[tx] = make_ulonglong2(pk2(cx, cx), pk2(cy, cy));
        sGH[tx] = make_ulonglong2(pk2(cz, cz), pk2(cw, cw));
    }
    if (tx == HID) { sbias[0] = bc[0]; sbias[1] = bc[1]; sbias[2] = bc[2]; sbias[3] = bd[0]; }
    __syncthreads();

    const int warp = tx >> 5;
    const int lane = tx & 31;
    const int r = blockIdx.x * WARPS_PER_BLOCK + warp;

    const float ox = o[3 * r], oy = o[3 * r + 1], oz = o[3 * r + 2];
    const float dx = dI[3 * r], dy = dI[3 * r + 1], dz = dI[3 * r + 2];
    const float mn0 = aabb[0], mn1 = aabb[1], mn2 = aabb[2];
    const float mx0 = aabb[3], mx1 = aabb[4], mx2 = aabb[5];

    float t1, t2;
    t1 = (mn0 - ox) / dx; t2 = (mx0 - ox) / dx;
    float tn = fminf(t1, t2), tf = fmaxf(t1, t2);
    t1 = (mn1 - oy) / dy; t2 = (mx1 - oy) / dy;
    tn = fmaxf(tn, fminf(t1, t2)); tf = fminf(tf, fmaxf(t1, t2));
    t1 = (mn2 - oz) / dz; t2 = (mx2 - oz) / dz;
    tn = fmaxf(tn, fminf(t1, t2)); tf = fminf(tf, fmaxf(t1, t2));
    tn = fmaxf(tn, 0.0f);

    if (!(tn < tf)) {
        if (lane == 0) reinterpret_cast<float4*>(out)[r] = make_float4(0.f, 0.f, 0.f, 0.f);
        return;
    }

    const float dnorm  = sqrtf(dx * dx + dy * dy + dz * dz);
    const float scaleT = (tf - tn) * (1.0f / (float)N_SAMPLES);
    const float dscale = scaleT * dnorm;
    const float g0 = 2.0f / (mx0 - mn0);
    const float g1 = 2.0f / (mx1 - mn1);
    const float g2 = 2.0f / (mx2 - mn2);
    const float bcr = sbias[0], bcg = sbias[1], bcb = sbias[2], bdd = sbias[3];

    const float4* u4 = reinterpret_cast<const float4*>(u + (size_t)r * N_SAMPLES) + lane * 4;
    float4 uv = u4[0];
    const float nb = __shfl_down_sync(FULL, uv.x, 1);   // lane 31's value unused (t==511 path)

    const int base = lane * TPT;

    float e_run = 1.0f, Psum = 0.0f;
    float ar = 0.f, ag = 0.f, ab = 0.f, aw = 0.f;

    #pragma unroll 1
    for (int i = 0; i < 4; ++i) {
        const float u0 = uv.x, u1 = uv.y, u2v = uv.z, u3 = uv.w;
        float un;
        if (i < 3) { uv = u4[i + 1]; un = uv.x; }
        else       { un = nb; }
        const int t0 = base + 4 * i;

        // ---- geometry for 4 samples
        float n00, n01, n02, n10, n11, n12, n20, n21, n22, n30, n31, n32, ts3;
        {
            const float ts = fmaf(scaleT, (float)(t0 + 0) + u0, tn);
            const float x = fmaf(dx, ts, ox), y = fmaf(dy, ts, oy), z = fmaf(dz, ts, oz);
            n00 = fmaf(x - mn0, g0, -1.0f); n01 = fmaf(y - mn1, g1, -1.0f); n02 = fmaf(z - mn2, g2, -1.0f);
        }
        {
            const float ts = fmaf(scaleT, (float)(t0 + 1) + u1, tn);
            const float x = fmaf(dx, ts, ox), y = fmaf(dy, ts, oy), z = fmaf(dz, ts, oz);
            n10 = fmaf(x - mn0, g0, -1.0f); n11 = fmaf(y - mn1, g1, -1.0f); n12 = fmaf(z - mn2, g2, -1.0f);
        }
        {
            const float ts = fmaf(scaleT, (float)(t0 + 2) + u2v, tn);
            const float x = fmaf(dx, ts, ox), y = fmaf(dy, ts, oy), z = fmaf(dz, ts, oz);
            n20 = fmaf(x - mn0, g0, -1.0f); n21 = fmaf(y - mn1, g1, -1.0f); n22 = fmaf(z - mn2, g2, -1.0f);
        }
        {
            ts3 = fmaf(scaleT, (float)(t0 + 3) + u3, tn);
            const float x = fmaf(dx, ts3, ox), y = fmaf(dy, ts3, oy), z = fmaf(dz, ts3, oz);
            n30 = fmaf(x - mn0, g0, -1.0f); n31 = fmaf(y - mn1, g1, -1.0f); n32 = fmaf(z - mn2, g2, -1.0f);
        }
        const bool ib0 = (fabsf(n00) <= 1.f) & (fabsf(n01) <= 1.f) & (fabsf(n02) <= 1.f);
        const bool ib1 = (fabsf(n10) <= 1.f) & (fabsf(n11) <= 1.f) & (fabsf(n12) <= 1.f);
        const bool ib2 = (fabsf(n20) <= 1.f) & (fabsf(n21) <= 1.f) & (fabsf(n22) <= 1.f);
        const bool ib3 = (fabsf(n30) <= 1.f) & (fabsf(n31) <= 1.f) & (fabsf(n32) <= 1.f);
        const float dl0 = dscale * (1.0f + u1 - u0);
        const float dl1 = dscale * (1.0f + u2v - u1);
        const float dl2 = dscale * (1.0f + u3 - u2v);
        float dl3 = dscale * (1.0f + un - u3);
        if (t0 + 3 == N_SAMPLES - 1) dl3 = (tf + 1.0f - ts3) * dnorm;

        // ---- packed MLP: pack a = (s0,s1), pack b = (s2,s3); weights loaded once per j
        const ull pn0a = pk2(n00, n10), pn1a = pk2(n01, n11), pn2a = pk2(n02, n12);
        const ull pn0b = pk2(n20, n30), pn1b = pk2(n21, n31), pn2b = pk2(n22, n32);

        ull pra = 0, pga = 0, pba = 0, pda = 0;
        ull prb = 0, pgb = 0, pbb = 0, pdb = 0;
        #pragma unroll 4
        for (int j = 0; j < HID; ++j) {
            const ulonglong2 wab = sAB[j];
            const ulonglong2 wcd = sCD[j];
            ull ha = fma2_(pn0a, wab.x, fma2_(pn1a, wab.y, fma2_(pn2a, wcd.x, wcd.y)));
            ull hb = fma2_(pn0b, wab.x, fma2_(pn1b, wab.y, fma2_(pn2b, wcd.x, wcd.y)));
            ha = relu2x(ha);
            hb = relu2x(hb);
            const ulonglong2 wef = sEF[j];
            const ulonglong2 wgh = sGH[j];
            pra = fma2_(ha, wef.x, pra); pga = fma2_(ha, wef.y, pga);
            pba = fma2_(ha, wgh.x, pba); pda = fma2_(ha, wgh.y, pda);
            prb = fma2_(hb, wef.x, prb); pgb = fma2_(hb, wef.y, pgb);
            pbb = fma2_(hb, wgh.x, pbb); pdb = fma2_(hb, wgh.y, pdb);
        }

        float c0r, c1r, c0g, c1g, c0b, c1b, d0, d1;
        float c2r, c3r, c2g, c3g, c2b, c3b, d2, d3;
        upk2(pra, c0r, c1r); upk2(pga, c0g, c1g); upk2(pba, c0b, c1b); upk2(pda, d0, d1);
        upk2(prb, c2r, c3r); upk2(pgb, c2g, c3g); upk2(pbb, c2b, c3b); upk2(pdb, d2, d3);

        // ---- sequential compositing (order matters)
        {
            const float cr = sigmoidf_fast(c0r + bcr), cg = sigmoidf_fast(c0g + bcg), cb = sigmoidf_fast(c0b + bcb);
            float den = softplusf_fast(d0 + bdd); if (!ib0) den = 0.0f;
            const float sd = den * dl0, esd = __expf(-sd);
            const float wl = e_run - e_run * esd;
            ar = fmaf(wl, cr, ar); ag = fmaf(wl, cg, ag); ab = fmaf(wl, cb, ab); aw += wl;
            e_run *= esd; Psum += sd;
        }
        {
            const float cr = sigmoidf_fast(c1r + bcr), cg = sigmoidf_fast(c1g + bcg), cb = sigmoidf_fast(c1b + bcb);
            float den = softplusf_fast(d1 + bdd); if (!ib1) den = 0.0f;
            const float sd = den * dl1, esd = __expf(-sd);
            const float wl = e_run - e_run * esd;
            ar = fmaf(wl, cr, ar); ag = fmaf(wl, cg, ag); ab = fmaf(wl, cb, ab); aw += wl;
            e_run *= esd; Psum += sd;
        }
        {
            const float cr = sigmoidf_fast(c2r + bcr), cg = sigmoidf_fast(c2g + bcg), cb = sigmoidf_fast(c2b + bcb);
            float den = softplusf_fast(d2 + bdd); if (!ib2) den = 0.0f;
            const float sd = den * dl2, esd = __expf(-sd);
            const float wl = e_run - e_run * esd;
            ar = fmaf(wl, cr, ar); ag = fmaf(wl, cg, ag); ab = fmaf(wl, cb, ab); aw += wl;
            e_run *= esd; Psum += sd;
        }
        {
            const float cr = sigmoidf_fast(c3r + bcr), cg = sigmoidf_fast(c3g + bcg), cb = sigmoidf_fast(c3b + bcb);
            float den = softplusf_fast(d3 + bdd); if (!ib3) den = 0.0f;
            const float sd = den * dl3, esd = __expf(-sd);
            const float wl = e_run - e_run * esd;
            ar = fmaf(wl, cr, ar); ag = fmaf(wl, cg, ag); ab = fmaf(wl, cb, ab); aw += wl;
            e_run *= esd; Psum += sd;
        }
    }

    // ---- warp exclusive scan of optical depth -> per-lane transmittance base
    float inc = Psum;
    #pragma unroll
    for (int off = 1; off < 32; off <<= 1) {
        float y = __shfl_up_sync(FULL, inc, off);
        if (lane >= off) inc += y;
    }
    float excl = __shfl_up_sync(FULL, inc, 1);
    if (lane == 0) excl = 0.0f;
    const float sc = __expf(-excl);
    ar *= sc; ag *= sc; ab *= sc; aw *= sc;

    #pragma unroll
    for (int off = 16; off > 0; off >>= 1) {
        ar += __shfl_xor_sync(FULL, ar, off);
        ag += __shfl_xor_sync(FULL, ag, off);
        ab += __shfl_xor_sync(FULL, ab, off);
        aw += __shfl_xor_sync(FULL, aw, off);
    }

    if (lane == 0)
        reinterpret_cast<float4*>(out)[r] = make_float4(ar, ag, ab, aw);
}

extern "C" void kernel_launch(void* const* d_in, const int* in_sizes, int n_in,
                              void* d_out, int out_size) {
    const float* o    = (const float*)d_in[0];
    const float* dI   = (const float*)d_in[1];
    const float* aabb = (const float*)d_in[2];
    const float* u    = (const float*)d_in[3];
    const float* W1   = (const float*)d_in[4];
    const float* b1   = (const float*)d_in[5];
    const float* Wc   = (const float*)d_in[6];
    const float* bc   = (const float*)d_in[7];
    const float* Wd   = (const float*)d_in[8];
    const float* bd   = (const float*)d_in[9];
    float* out = (float*)d_out;

    dim3 grid(N_RAYS / WARPS_PER_BLOCK);
    dim3 block(WARPS_PER_BLOCK * 32);
    nerf_render_kernel<<<grid, block>>>(o, dI, aabb, u, W1, b1, Wc, bc, Wd, bd, out);
}